// round 9
// baseline (speedup 1.0000x reference)
#include <cuda_runtime.h>
#include <cuda_bf16.h>
#include <math.h>

// Problem constants
#define BB   32
#define SS   2048
#define EE   512
#define NCc  128
#define NTt  32
#define HH   8
#define QQ   4

// split-K chunk counts (KC = K/chunks must be a multiple of 32)
#define CH_BOX   48
#define CH_GATES 24
#define CH_ATT   32

#define NCHUNK 32   // ctx partial chunks
#define NPAD   36   // shared row pad (floats): 16B-aligned rows, 2-way conflicts max

typedef unsigned long long ull;

// ---------------- device scratch (no allocations allowed) ----------------
__device__ float g_boxA [BB * 3 * EE];          // [head_emb | body_emb | box_op_e]
__device__ float g_lstmA[BB * 3 * EE];          // [encoded_box | att | h0]
__device__ float g_hc   [BB * 2 * EE];          // [h | ctx]
__device__ float g_scores[BB * SS];
__device__ float g_attw  [BB * SS];
__device__ float g_part  [BB * NCHUNK * EE];        // ctx partials
__device__ float g_pbox  [CH_BOX   * BB * EE];      // box gemm partials
__device__ float g_pgates[CH_GATES * BB * 4 * EE];  // gates gemm partials
__device__ float g_patt  [CH_ATT   * BB * EE];      // att gemm partials
__device__ int   g_mask_mode;                       // 0=int32, 1=float32, 2=uint8

__device__ __forceinline__ void ffma2(ull& d, ull a, ull b) {
    asm("fma.rn.f32x2 %0, %1, %2, %0;" : "+l"(d) : "l"(a), "l"(b));
}
__device__ __forceinline__ void cpa16(unsigned s, const void* g) {
    asm volatile("cp.async.cg.shared.global [%0], [%1], 16;" :: "r"(s), "l"(g));
}
__device__ __forceinline__ void cp_commit() {
    asm volatile("cp.async.commit_group;");
}
template <int N> __device__ __forceinline__ void cp_wait() {
    asm volatile("cp.async.wait_group %0;" :: "n"(N));
}

// ---------------- prep (blocks 0..31) + mask sniff (block 32) ----------------
__global__ void prep_detect_kernel(const float* __restrict__ agg_emb,
                                   const float* __restrict__ encoded_col,
                                   const float* __restrict__ encoded_tab,
                                   const float* __restrict__ box_op_emb,
                                   const int* __restrict__ head_agg,
                                   const int* __restrict__ head_col,
                                   const int* __restrict__ quant_tab,
                                   const int* __restrict__ box_op,
                                   const float* __restrict__ att,
                                   const float* __restrict__ h0,
                                   const unsigned int* __restrict__ maskw) {
    int e = threadIdx.x;                 // 512 threads
    if (blockIdx.x == BB) {
        __shared__ int s_ok32, s_okf;
        if (e == 0) { s_ok32 = 1; s_okf = 1; }
        __syncthreads();
        int ok32 = 1, okf = 1;
        for (int i = e; i < 2048; i += 512) {
            unsigned v = maskw[i];
            if (v > 1u) ok32 = 0;
            if (v != 0u && v != 0x3F800000u) okf = 0;
        }
        if (!ok32) atomicAnd(&s_ok32, 0);
        if (!okf)  atomicAnd(&s_okf, 0);
        __syncthreads();
        if (e == 0) g_mask_mode = s_ok32 ? 0 : (s_okf ? 1 : 2);
        return;
    }
    int b = blockIdx.x;
    __shared__ int ia[HH], ic[HH], iq[QQ], ib;
    if (e < HH) ia[e] = head_agg[b * HH + e];
    else if (e < 2 * HH) ic[e - HH] = head_col[b * HH + (e - HH)];
    else if (e < 2 * HH + QQ) iq[e - 2 * HH] = quant_tab[b * QQ + (e - 2 * HH)];
    else if (e == 2 * HH + QQ) ib = box_op[b];
    __syncthreads();

    float he = 0.f;
#pragma unroll
    for (int h = 0; h < HH; h++)
        he += agg_emb[ia[h] * EE + e] + encoded_col[((size_t)b * NCc + ic[h]) * EE + e];
    he *= (1.0f / HH);
    float be = 0.f;
#pragma unroll
    for (int q = 0; q < QQ; q++)
        be += encoded_tab[((size_t)b * NTt + iq[q]) * EE + e];
    be *= (1.0f / QQ);

    float* boxA = g_boxA + (size_t)b * 3 * EE;
    boxA[e]          = he;
    boxA[EE + e]     = be;
    boxA[2 * EE + e] = box_op_emb[ib * EE + e];

    float* lA = g_lstmA + (size_t)b * 3 * EE;
    lA[EE + e]     = att[b * EE + e];
    lA[2 * EE + e] = h0[b * EE + e];
}

// ---------------- cp.async + FFMA2 split-K GEMM ----------------
// Tile 32b x 64n, KT=32 per stage, cp.async 2-stage pipeline.
// 128 threads; thread computes 4b x 4n via packed fma.rn.f32x2.
// W columns k<K1 from W1 (row stride K1), rest W2 (row stride K-K1).
__global__ void __launch_bounds__(128)
gemm_cp_kernel(const float* __restrict__ A, int K,
               const float* __restrict__ W1, int K1,
               const float* __restrict__ W2,
               float* __restrict__ part, int Ntot) {
    __shared__ __align__(16) float As[2][32][NPAD];
    __shared__ __align__(16) float Ws[2][64][NPAD];
    int tid = threadIdx.x;               // 128
    int n0  = blockIdx.x * 64;
    int KC  = K / gridDim.y;
    int kb  = blockIdx.y * KC;
    int T   = KC / 32;
    int K2len = K - K1;

    unsigned as_s = (unsigned)__cvta_generic_to_shared(&As[0][0][0]);
    unsigned ws_s = (unsigned)__cvta_generic_to_shared(&Ws[0][0][0]);

    // loader mapping: q = k-quarter (0..7), r = row base (0..15)
    int q = tid & 7, r = tid >> 3;
    // compute mapping
    int ng = tid & 15, bg = tid >> 4;

    ull acc[4][4];
#pragma unroll
    for (int i = 0; i < 4; i++)
#pragma unroll
        for (int j = 0; j < 4; j++) acc[i][j] = 0ull;

#define G_LOAD(buf, k0)                                                        \
    {                                                                          \
        int kg = (k0) + q * 4;                                                 \
        _Pragma("unroll")                                                      \
        for (int m = 0; m < 4; m++) {                                          \
            int row = r + 16 * m;                                              \
            const float* src = (kg < K1)                                       \
                ? (W1 + (size_t)(n0 + row) * K1 + kg)                          \
                : (W2 + (size_t)(n0 + row) * K2len + (kg - K1));               \
            cpa16(ws_s + (unsigned)((((buf) * 64 + row) * NPAD + q * 4) * 4),  \
                  src);                                                        \
        }                                                                      \
        cpa16(as_s + (unsigned)((((buf) * 32 + r) * NPAD + q * 4) * 4),        \
              A + (size_t)r * K + kg);                                         \
        cpa16(as_s + (unsigned)((((buf) * 32 + r + 16) * NPAD + q * 4) * 4),   \
              A + (size_t)(r + 16) * K + kg);                                  \
        cp_commit();                                                           \
    }

    G_LOAD(0, kb);
    if (T > 1) G_LOAD(1, kb + 32);

    for (int t = 0; t < T; t++) {
        if (t + 1 < T) cp_wait<1>(); else cp_wait<0>();
        __syncthreads();
        int buf = t & 1;
        const ull* As64 = (const ull*)&As[buf][0][0];   // row stride NPAD/2
        const ull* Ws64 = (const ull*)&Ws[buf][0][0];
#pragma unroll
        for (int k2 = 0; k2 < 16; k2++) {
            ull a[4], w[4];
#pragma unroll
            for (int i = 0; i < 4; i++)
                a[i] = As64[(size_t)(bg + 8 * i) * (NPAD / 2) + k2];
#pragma unroll
            for (int j = 0; j < 4; j++)
                w[j] = Ws64[(size_t)(ng + 16 * j) * (NPAD / 2) + k2];
#pragma unroll
            for (int i = 0; i < 4; i++)
#pragma unroll
                for (int j = 0; j < 4; j++)
                    ffma2(acc[i][j], a[i], w[j]);
        }
        __syncthreads();
        if (t + 2 < T) G_LOAD(buf, kb + (t + 2) * 32);
    }

    float* dst = part + (size_t)(blockIdx.y * 32) * Ntot;
#pragma unroll
    for (int i = 0; i < 4; i++) {
        int b = bg + 8 * i;
#pragma unroll
        for (int j = 0; j < 4; j++) {
            int n = n0 + ng + 16 * j;
            ull v = acc[i][j];
            float lo = __uint_as_float((unsigned)(v & 0xFFFFFFFFull));
            float hi = __uint_as_float((unsigned)(v >> 32));
            dst[(size_t)b * Ntot + n] = lo + hi;
        }
    }
#undef G_LOAD
}

// ---------------- reduce split-K partials + bias (+relu), float4 ----------------
__global__ void reduce_act4_kernel(const float4* __restrict__ part, int nchunks,
                                   int N4, const float4* __restrict__ bias,
                                   float4* __restrict__ out, int ldo4, int relu) {
    int idx = blockIdx.x * blockDim.x + threadIdx.x;   // 32*N4 items
    int b = idx / N4, n = idx - b * N4;
    float4 s = make_float4(0.f, 0.f, 0.f, 0.f);
#pragma unroll 16
    for (int c = 0; c < nchunks; c++) {
        float4 p = part[(size_t)(c * 32 + b) * N4 + n];
        s.x += p.x; s.y += p.y; s.z += p.z; s.w += p.w;
    }
    float4 bb = bias[n];
    s.x += bb.x; s.y += bb.y; s.z += bb.z; s.w += bb.w;
    if (relu) {
        s.x = fmaxf(s.x, 0.f); s.y = fmaxf(s.y, 0.f);
        s.z = fmaxf(s.z, 0.f); s.w = fmaxf(s.w, 0.f);
    }
    out[(size_t)b * ldo4 + n] = s;
}

// ---------------- LSTM elementwise, float4, reduces gates partials ----------
__device__ __forceinline__ float sigmf(float x) { return 1.0f / (1.0f + expf(-x)); }

__global__ void lstm_elem4_kernel(const float4* __restrict__ c0,
                                  const float4* __restrict__ b_ih,
                                  const float4* __restrict__ b_hh) {
    int idx = blockIdx.x * blockDim.x + threadIdx.x;   // 32*128
    int b = idx >> 7, e4 = idx & 127;
    float4 gi = make_float4(0,0,0,0), gf = gi, gg = gi, go = gi;
#pragma unroll
    for (int c = 0; c < CH_GATES; c++) {
        const float4* g = (const float4*)(g_pgates + (size_t)(c * 32 + b) * 4 * EE);
        float4 a = g[e4], f = g[128 + e4], x = g[256 + e4], o = g[384 + e4];
        gi.x += a.x; gi.y += a.y; gi.z += a.z; gi.w += a.w;
        gf.x += f.x; gf.y += f.y; gf.z += f.z; gf.w += f.w;
        gg.x += x.x; gg.y += x.y; gg.z += x.z; gg.w += x.w;
        go.x += o.x; go.y += o.y; go.z += o.z; go.w += o.w;
    }
    float4 bi = b_ih[e4],        bh = b_hh[e4];
    float4 bf = b_ih[128 + e4],  bf2 = b_hh[128 + e4];
    float4 bg = b_ih[256 + e4],  bg2 = b_hh[256 + e4];
    float4 bo = b_ih[384 + e4],  bo2 = b_hh[384 + e4];
    gi.x += bi.x + bh.x;  gi.y += bi.y + bh.y;  gi.z += bi.z + bh.z;  gi.w += bi.w + bh.w;
    gf.x += bf.x + bf2.x; gf.y += bf.y + bf2.y; gf.z += bf.z + bf2.z; gf.w += bf.w + bf2.w;
    gg.x += bg.x + bg2.x; gg.y += bg.y + bg2.y; gg.z += bg.z + bg2.z; gg.w += bg.w + bg2.w;
    go.x += bo.x + bo2.x; go.y += bo.y + bo2.y; go.z += bo.z + bo2.z; go.w += bo.w + bo2.w;
    float4 cc = c0[b * 128 + e4];
    float4 h;
    {
        float c1 = sigmf(gf.x) * cc.x + sigmf(gi.x) * tanhf(gg.x); h.x = sigmf(go.x) * tanhf(c1);
        float c2 = sigmf(gf.y) * cc.y + sigmf(gi.y) * tanhf(gg.y); h.y = sigmf(go.y) * tanhf(c2);
        float c3 = sigmf(gf.z) * cc.z + sigmf(gi.z) * tanhf(gg.z); h.z = sigmf(go.z) * tanhf(c3);
        float c4 = sigmf(gf.w) * cc.w + sigmf(gi.w) * tanhf(gg.w); h.w = sigmf(go.w) * tanhf(c4);
    }
    ((float4*)g_hc)[(size_t)b * 256 + e4] = h;   // h into [b][0:512)
}

// ---------------- attention scores: warp per source row ----------------
__global__ void scores_kernel(const float* __restrict__ src_att,
                              const void* __restrict__ maskp) {
    int b = blockIdx.y;
    int tid = threadIdx.x;               // 256 = 8 warps
    __shared__ __align__(16) float sh[EE];
    for (int i = tid; i < EE; i += 256) sh[i] = g_hc[(size_t)b * 2 * EE + i];
    __syncthreads();

    int warp = tid >> 5, lane = tid & 31;
    int s = blockIdx.x * 8 + warp;
    const float4* row = (const float4*)(src_att + ((size_t)b * SS + s) * EE);
    const float4* h4  = (const float4*)sh;
    float4 v0 = row[lane +  0], h0v = h4[lane +  0];
    float4 v1 = row[lane + 32], h1v = h4[lane + 32];
    float4 v2 = row[lane + 64], h2v = h4[lane + 64];
    float4 v3 = row[lane + 96], h3v = h4[lane + 96];
    float a0 = v0.x * h0v.x + v0.y * h0v.y + v0.z * h0v.z + v0.w * h0v.w;
    float a1 = v1.x * h1v.x + v1.y * h1v.y + v1.z * h1v.z + v1.w * h1v.w;
    float a2 = v2.x * h2v.x + v2.y * h2v.y + v2.z * h2v.z + v2.w * h2v.w;
    float a3 = v3.x * h3v.x + v3.y * h3v.y + v3.z * h3v.z + v3.w * h3v.w;
    float acc = (a0 + a1) + (a2 + a3);
#pragma unroll
    for (int off = 16; off > 0; off >>= 1)
        acc += __shfl_xor_sync(0xFFFFFFFF, acc, off);

    if (lane == 0) {
        int mm = g_mask_mode;
        bool masked;
        size_t mi = (size_t)b * SS + s;
        if (mm == 0)      masked = ((const int*)maskp)[mi] != 0;
        else if (mm == 1) masked = ((const float*)maskp)[mi] != 0.f;
        else              masked = ((const unsigned char*)maskp)[mi] != 0;
        g_scores[mi] = masked ? -INFINITY : acc;
    }
}

// ---------------- softmax over S per batch row ----------------
__global__ void softmax_kernel() {
    int b = blockIdx.x;
    int tid = threadIdx.x;               // 256
    const float* sc = g_scores + (size_t)b * SS;
    __shared__ float red[256];
    float m = -INFINITY;
    for (int s = tid; s < SS; s += 256) m = fmaxf(m, sc[s]);
    red[tid] = m; __syncthreads();
    for (int o = 128; o > 0; o >>= 1) { if (tid < o) red[tid] = fmaxf(red[tid], red[tid + o]); __syncthreads(); }
    float mx = red[0]; __syncthreads();
    float sum = 0.f;
    for (int s = tid; s < SS; s += 256) sum += expf(sc[s] - mx);
    red[tid] = sum; __syncthreads();
    for (int o = 128; o > 0; o >>= 1) { if (tid < o) red[tid] += red[tid + o]; __syncthreads(); }
    float inv = 1.0f / red[0];
    float* w = g_attw + (size_t)b * SS;
    for (int s = tid; s < SS; s += 256) w[s] = expf(sc[s] - mx) * inv;
}

// ---------------- ctx partials: block per (chunk, b) ----------------
__global__ void ctx_part_kernel(const float* __restrict__ src) {
    int ch = blockIdx.x, b = blockIdx.y;
    int tid = threadIdx.x;               // 128, each owns float4 of E
    const int ROWS = SS / NCHUNK;        // 64
    __shared__ float w[ROWS];
    if (tid < ROWS) w[tid] = g_attw[(size_t)b * SS + ch * ROWS + tid];
    __syncthreads();
    const float4* base = (const float4*)(src + ((size_t)b * SS + (size_t)ch * ROWS) * EE);
    float4 acc = make_float4(0.f, 0.f, 0.f, 0.f);
#pragma unroll 8
    for (int s = 0; s < ROWS; s++) {
        float4 v = base[(size_t)s * 128 + tid];
        float ws = w[s];
        acc.x = fmaf(ws, v.x, acc.x);
        acc.y = fmaf(ws, v.y, acc.y);
        acc.z = fmaf(ws, v.z, acc.z);
        acc.w = fmaf(ws, v.w, acc.w);
    }
    ((float4*)g_part)[((size_t)b * NCHUNK + ch) * 128 + tid] = acc;
}

// ---------------- reduce ctx partials into g_hc[:, E:], float4 ----------------
__global__ void ctx_reduce4_kernel() {
    int idx = blockIdx.x * blockDim.x + threadIdx.x;   // 32*128
    int b = idx >> 7, e4 = idx & 127;
    float4 s = make_float4(0.f, 0.f, 0.f, 0.f);
#pragma unroll
    for (int c = 0; c < NCHUNK; c++) {
        float4 p = ((const float4*)g_part)[((size_t)b * NCHUNK + c) * 128 + e4];
        s.x += p.x; s.y += p.y; s.z += p.z; s.w += p.w;
    }
    ((float4*)(g_hc + (size_t)b * 2 * EE + EE))[e4] = s;
}

// ---------------- launch ----------------
extern "C" void kernel_launch(void* const* d_in, const int* in_sizes, int n_in,
                              void* d_out, int out_size) {
    const float* encoded_src     = (const float*)d_in[0];
    const float* encoded_src_att = (const float*)d_in[1];
    const float* encoded_col     = (const float*)d_in[2];
    const float* encoded_tab     = (const float*)d_in[3];
    const void*  src_mask        = d_in[4];
    const float* att             = (const float*)d_in[5];
    const float* h0              = (const float*)d_in[6];
    const float* c0              = (const float*)d_in[7];
    const int*   head_agg        = (const int*)d_in[8];
    const int*   head_col        = (const int*)d_in[9];
    const int*   quant_tab       = (const int*)d_in[10];
    const int*   box_op          = (const int*)d_in[11];
    const float* agg_emb         = (const float*)d_in[12];
    const float* box_op_emb      = (const float*)d_in[13];
    const float* W_box           = (const float*)d_in[14];
    const float* b_box           = (const float*)d_in[15];
    const float* W_ih            = (const float*)d_in[16];
    const float* W_hh            = (const float*)d_in[17];
    const float* b_ih            = (const float*)d_in[18];
    const float* b_hh            = (const float*)d_in[19];
    const float* W_att           = (const float*)d_in[20];
    const float* b_att           = (const float*)d_in[21];
    float* out = (float*)d_out;

    float *p_boxA, *p_lstmA, *p_pbox, *p_pgates, *p_patt, *p_hc;
    cudaGetSymbolAddress((void**)&p_boxA, g_boxA);
    cudaGetSymbolAddress((void**)&p_lstmA, g_lstmA);
    cudaGetSymbolAddress((void**)&p_hc, g_hc);
    cudaGetSymbolAddress((void**)&p_pbox, g_pbox);
    cudaGetSymbolAddress((void**)&p_pgates, g_pgates);
    cudaGetSymbolAddress((void**)&p_patt, g_patt);

    // 1. prep + mask sniff
    prep_detect_kernel<<<BB + 1, EE>>>(agg_emb, encoded_col, encoded_tab,
                                       box_op_emb, head_agg, head_col,
                                       quant_tab, box_op, att, h0,
                                       (const unsigned int*)src_mask);

    // 2. box GEMM partials (KC=32) + reduce+relu -> g_lstmA[:, :E]
    gemm_cp_kernel<<<dim3(EE / 64, CH_BOX), 128>>>(
        p_boxA, 3 * EE, W_box, 3 * EE, nullptr, p_pbox, EE);
    reduce_act4_kernel<<<(BB * EE / 4) / 256, 256>>>(
        (const float4*)p_pbox, CH_BOX, EE / 4, (const float4*)b_box,
        (float4*)p_lstmA, (3 * EE) / 4, 1);

    // 3. gates GEMM partials (KC=64)
    gemm_cp_kernel<<<dim3((4 * EE) / 64, CH_GATES), 128>>>(
        p_lstmA, 3 * EE, W_ih, 2 * EE, W_hh, p_pgates, 4 * EE);

    // 4. LSTM elementwise (reduces partials + biases) -> h in g_hc[:, :E]
    lstm_elem4_kernel<<<(BB * EE / 4) / 256, 256>>>(
        (const float4*)c0, (const float4*)b_ih, (const float4*)b_hh);

    // 5. attention scores (134 MB stream)
    scores_kernel<<<dim3(SS / 8, BB), 256>>>(encoded_src_att, src_mask);

    // 6. softmax
    softmax_kernel<<<BB, 256>>>();

    // 7. ctx partials (134 MB stream)
    ctx_part_kernel<<<dim3(NCHUNK, BB), 128>>>(encoded_src);

    // 8. reduce -> g_hc[:, E:]
    ctx_reduce4_kernel<<<(BB * EE / 4) / 256, 256>>>();

    // 9. att GEMM partials (KC=32) + reduce+relu -> d_out
    gemm_cp_kernel<<<dim3(EE / 64, CH_ATT), 128>>>(
        p_hc, 2 * EE, W_att, 2 * EE, nullptr, p_patt, EE);
    reduce_act4_kernel<<<(BB * EE / 4) / 256, 256>>>(
        (const float4*)p_patt, CH_ATT, EE / 4, (const float4*)b_att,
        (float4*)out, EE / 4, 1);
}

// round 12
// speedup vs baseline: 1.0168x; 1.0168x over previous
#include <cuda_runtime.h>
#include <cuda_bf16.h>
#include <math.h>

// Problem constants
#define BB   32
#define SS   2048
#define EE   512
#define NCc  128
#define NTt  32
#define HH   8
#define QQ   4

// split-K chunk counts (KC = K/chunks must be a multiple of 32)
#define CH_BOX   48
#define CH_GATES 24
#define CH_ATT   32

#define NCHUNK 32   // ctx partial chunks
#define NPAD   36   // shared row pad (floats): 16B-aligned rows

typedef unsigned long long ull;

// ---------------- device scratch (no allocations allowed) ----------------
__device__ float g_boxA [BB * 3 * EE];          // [head_emb | body_emb | box_op_e]
__device__ float g_lstmA[BB * 3 * EE];          // [encoded_box | att | h0]
__device__ float g_hc   [BB * 2 * EE];          // [h | ctx]
__device__ float g_scores[BB * SS];
__device__ float g_attw  [BB * SS];
__device__ float g_part  [BB * NCHUNK * EE];        // ctx partials
__device__ float g_pbox  [CH_BOX   * BB * EE];      // box gemm partials
__device__ float g_pgates[CH_GATES * BB * 4 * EE];  // gates gemm partials
__device__ float g_patt  [CH_ATT   * BB * EE];      // att gemm partials
__device__ int   g_mask_mode;                       // 0=int32, 1=float32, 2=uint8

__device__ __forceinline__ void ffma2(ull& d, ull a, ull b) {
    asm("fma.rn.f32x2 %0, %1, %2, %0;" : "+l"(d) : "l"(a), "l"(b));
}
__device__ __forceinline__ void cpa16(unsigned s, const void* g) {
    asm volatile("cp.async.cg.shared.global [%0], [%1], 16;" :: "r"(s), "l"(g));
}
__device__ __forceinline__ void cp_commit() {
    asm volatile("cp.async.commit_group;");
}
template <int N> __device__ __forceinline__ void cp_wait() {
    asm volatile("cp.async.wait_group %0;" :: "n"(N));
}

// ---------------- prep (blocks 0..31) + mask sniff (block 32) ----------------
__global__ void prep_detect_kernel(const float* __restrict__ agg_emb,
                                   const float* __restrict__ encoded_col,
                                   const float* __restrict__ encoded_tab,
                                   const float* __restrict__ box_op_emb,
                                   const int* __restrict__ head_agg,
                                   const int* __restrict__ head_col,
                                   const int* __restrict__ quant_tab,
                                   const int* __restrict__ box_op,
                                   const float* __restrict__ att,
                                   const float* __restrict__ h0,
                                   const unsigned int* __restrict__ maskw) {
    int e = threadIdx.x;                 // 512 threads
    if (blockIdx.x == BB) {
        __shared__ int s_ok32, s_okf;
        if (e == 0) { s_ok32 = 1; s_okf = 1; }
        __syncthreads();
        int ok32 = 1, okf = 1;
        for (int i = e; i < 2048; i += 512) {
            unsigned v = maskw[i];
            if (v > 1u) ok32 = 0;
            if (v != 0u && v != 0x3F800000u) okf = 0;
        }
        if (!ok32) atomicAnd(&s_ok32, 0);
        if (!okf)  atomicAnd(&s_okf, 0);
        __syncthreads();
        if (e == 0) g_mask_mode = s_ok32 ? 0 : (s_okf ? 1 : 2);
        return;
    }
    int b = blockIdx.x;
    __shared__ int ia[HH], ic[HH], iq[QQ], ib;
    if (e < HH) ia[e] = head_agg[b * HH + e];
    else if (e < 2 * HH) ic[e - HH] = head_col[b * HH + (e - HH)];
    else if (e < 2 * HH + QQ) iq[e - 2 * HH] = quant_tab[b * QQ + (e - 2 * HH)];
    else if (e == 2 * HH + QQ) ib = box_op[b];
    __syncthreads();

    float he = 0.f;
#pragma unroll
    for (int h = 0; h < HH; h++)
        he += agg_emb[ia[h] * EE + e] + encoded_col[((size_t)b * NCc + ic[h]) * EE + e];
    he *= (1.0f / HH);
    float be = 0.f;
#pragma unroll
    for (int q = 0; q < QQ; q++)
        be += encoded_tab[((size_t)b * NTt + iq[q]) * EE + e];
    be *= (1.0f / QQ);

    float* boxA = g_boxA + (size_t)b * 3 * EE;
    boxA[e]          = he;
    boxA[EE + e]     = be;
    boxA[2 * EE + e] = box_op_emb[ib * EE + e];

    float* lA = g_lstmA + (size_t)b * 3 * EE;
    lA[EE + e]     = att[b * EE + e];
    lA[2 * EE + e] = h0[b * EE + e];
}

// ---------------- cp.async + FFMA2 split-K GEMM (LDS.128 inner loop) --------
// Tile 32b x 64n, KT=32 per stage, cp.async 2-stage pipeline.
// 128 threads; thread computes 4b x 4n via packed fma.rn.f32x2.
// Inner loop loads 16B (ulonglong2) per row per k4-chunk: LDS.128, no
// conflicts (a: 8 distinct rows = 128B; w: 16 distinct rows = 256B floor).
__global__ void __launch_bounds__(128)
gemm_cp_kernel(const float* __restrict__ A, int K,
               const float* __restrict__ W1, int K1,
               const float* __restrict__ W2,
               float* __restrict__ part, int Ntot) {
    __shared__ __align__(16) float As[2][32][NPAD];
    __shared__ __align__(16) float Ws[2][64][NPAD];
    int tid = threadIdx.x;               // 128
    int n0  = blockIdx.x * 64;
    int KC  = K / gridDim.y;
    int kb  = blockIdx.y * KC;
    int T   = KC / 32;
    int K2len = K - K1;

    unsigned as_s = (unsigned)__cvta_generic_to_shared(&As[0][0][0]);
    unsigned ws_s = (unsigned)__cvta_generic_to_shared(&Ws[0][0][0]);

    // loader mapping: q = k-quarter (0..7), r = row base (0..15)
    int q = tid & 7, r = tid >> 3;
    // compute mapping
    int ng = tid & 15, bg = tid >> 4;

    ull acc[4][4];
#pragma unroll
    for (int i = 0; i < 4; i++)
#pragma unroll
        for (int j = 0; j < 4; j++) acc[i][j] = 0ull;

#define G_LOAD(buf, k0)                                                        \
    {                                                                          \
        int kg = (k0) + q * 4;                                                 \
        _Pragma("unroll")                                                      \
        for (int m = 0; m < 4; m++) {                                          \
            int row = r + 16 * m;                                              \
            const float* src = (kg < K1)                                       \
                ? (W1 + (size_t)(n0 + row) * K1 + kg)                          \
                : (W2 + (size_t)(n0 + row) * K2len + (kg - K1));               \
            cpa16(ws_s + (unsigned)((((buf) * 64 + row) * NPAD + q * 4) * 4),  \
                  src);                                                        \
        }                                                                      \
        cpa16(as_s + (unsigned)((((buf) * 32 + r) * NPAD + q * 4) * 4),        \
              A + (size_t)r * K + kg);                                         \
        cpa16(as_s + (unsigned)((((buf) * 32 + r + 16) * NPAD + q * 4) * 4),   \
              A + (size_t)(r + 16) * K + kg);                                  \
        cp_commit();                                                           \
    }

    G_LOAD(0, kb);
    if (T > 1) G_LOAD(1, kb + 32);

    for (int t = 0; t < T; t++) {
        if (t + 1 < T) cp_wait<1>(); else cp_wait<0>();
        __syncthreads();
        int buf = t & 1;
#pragma unroll
        for (int k4 = 0; k4 < 8; k4++) {
            ulonglong2 a2[4], w2[4];
#pragma unroll
            for (int i = 0; i < 4; i++)
                a2[i] = *(const ulonglong2*)&As[buf][bg + 8 * i][k4 * 4];
#pragma unroll
            for (int j = 0; j < 4; j++)
                w2[j] = *(const ulonglong2*)&Ws[buf][ng + 16 * j][k4 * 4];
#pragma unroll
            for (int i = 0; i < 4; i++)
#pragma unroll
                for (int j = 0; j < 4; j++) {
                    ffma2(acc[i][j], a2[i].x, w2[j].x);
                    ffma2(acc[i][j], a2[i].y, w2[j].y);
                }
        }
        __syncthreads();
        if (t + 2 < T) G_LOAD(buf, kb + (t + 2) * 32);
    }

    float* dst = part + (size_t)(blockIdx.y * 32) * Ntot;
#pragma unroll
    for (int i = 0; i < 4; i++) {
        int b = bg + 8 * i;
#pragma unroll
        for (int j = 0; j < 4; j++) {
            int n = n0 + ng + 16 * j;
            ull v = acc[i][j];
            float lo = __uint_as_float((unsigned)(v & 0xFFFFFFFFull));
            float hi = __uint_as_float((unsigned)(v >> 32));
            dst[(size_t)b * Ntot + n] = lo + hi;
        }
    }
#undef G_LOAD
}

// ---------------- reduce split-K partials + bias (+relu), float4 ----------------
__global__ void reduce_act4_kernel(const float4* __restrict__ part, int nchunks,
                                   int N4, const float4* __restrict__ bias,
                                   float4* __restrict__ out, int ldo4, int relu) {
    int idx = blockIdx.x * blockDim.x + threadIdx.x;   // 32*N4 items
    int b = idx / N4, n = idx - b * N4;
    float4 s = make_float4(0.f, 0.f, 0.f, 0.f);
#pragma unroll 16
    for (int c = 0; c < nchunks; c++) {
        float4 p = part[(size_t)(c * 32 + b) * N4 + n];
        s.x += p.x; s.y += p.y; s.z += p.z; s.w += p.w;
    }
    float4 bb = bias[n];
    s.x += bb.x; s.y += bb.y; s.z += bb.z; s.w += bb.w;
    if (relu) {
        s.x = fmaxf(s.x, 0.f); s.y = fmaxf(s.y, 0.f);
        s.z = fmaxf(s.z, 0.f); s.w = fmaxf(s.w, 0.f);
    }
    out[(size_t)b * ldo4 + n] = s;
}

// ---------------- LSTM elementwise, float4, reduces gates partials ----------
__device__ __forceinline__ float sigmf(float x) { return 1.0f / (1.0f + expf(-x)); }

__global__ void lstm_elem4_kernel(const float4* __restrict__ c0,
                                  const float4* __restrict__ b_ih,
                                  const float4* __restrict__ b_hh) {
    int idx = blockIdx.x * blockDim.x + threadIdx.x;   // 32*128
    int b = idx >> 7, e4 = idx & 127;
    float4 gi = make_float4(0,0,0,0), gf = gi, gg = gi, go = gi;
#pragma unroll
    for (int c = 0; c < CH_GATES; c++) {
        const float4* g = (const float4*)(g_pgates + (size_t)(c * 32 + b) * 4 * EE);
        float4 a = g[e4], f = g[128 + e4], x = g[256 + e4], o = g[384 + e4];
        gi.x += a.x; gi.y += a.y; gi.z += a.z; gi.w += a.w;
        gf.x += f.x; gf.y += f.y; gf.z += f.z; gf.w += f.w;
        gg.x += x.x; gg.y += x.y; gg.z += x.z; gg.w += x.w;
        go.x += o.x; go.y += o.y; go.z += o.z; go.w += o.w;
    }
    float4 bi = b_ih[e4],        bh = b_hh[e4];
    float4 bf = b_ih[128 + e4],  bf2 = b_hh[128 + e4];
    float4 bg = b_ih[256 + e4],  bg2 = b_hh[256 + e4];
    float4 bo = b_ih[384 + e4],  bo2 = b_hh[384 + e4];
    gi.x += bi.x + bh.x;  gi.y += bi.y + bh.y;  gi.z += bi.z + bh.z;  gi.w += bi.w + bh.w;
    gf.x += bf.x + bf2.x; gf.y += bf.y + bf2.y; gf.z += bf.z + bf2.z; gf.w += bf.w + bf2.w;
    gg.x += bg.x + bg2.x; gg.y += bg.y + bg2.y; gg.z += bg.z + bg2.z; gg.w += bg.w + bg2.w;
    go.x += bo.x + bo2.x; go.y += bo.y + bo2.y; go.z += bo.z + bo2.z; go.w += bo.w + bo2.w;
    float4 cc = c0[b * 128 + e4];
    float4 h;
    {
        float c1 = sigmf(gf.x) * cc.x + sigmf(gi.x) * tanhf(gg.x); h.x = sigmf(go.x) * tanhf(c1);
        float c2 = sigmf(gf.y) * cc.y + sigmf(gi.y) * tanhf(gg.y); h.y = sigmf(go.y) * tanhf(c2);
        float c3 = sigmf(gf.z) * cc.z + sigmf(gi.z) * tanhf(gg.z); h.z = sigmf(go.z) * tanhf(c3);
        float c4 = sigmf(gf.w) * cc.w + sigmf(gi.w) * tanhf(gg.w); h.w = sigmf(go.w) * tanhf(c4);
    }
    ((float4*)g_hc)[(size_t)b * 256 + e4] = h;   // h into [b][0:512)
}

// ---------------- attention scores: warp per source row ----------------
__global__ void scores_kernel(const float* __restrict__ src_att,
                              const void* __restrict__ maskp) {
    int b = blockIdx.y;
    int tid = threadIdx.x;               // 256 = 8 warps
    __shared__ __align__(16) float sh[EE];
    for (int i = tid; i < EE; i += 256) sh[i] = g_hc[(size_t)b * 2 * EE + i];
    __syncthreads();

    int warp = tid >> 5, lane = tid & 31;
    int s = blockIdx.x * 8 + warp;
    const float4* row = (const float4*)(src_att + ((size_t)b * SS + s) * EE);
    const float4* h4  = (const float4*)sh;
    float4 v0 = row[lane +  0], h0v = h4[lane +  0];
    float4 v1 = row[lane + 32], h1v = h4[lane + 32];
    float4 v2 = row[lane + 64], h2v = h4[lane + 64];
    float4 v3 = row[lane + 96], h3v = h4[lane + 96];
    float a0 = v0.x * h0v.x + v0.y * h0v.y + v0.z * h0v.z + v0.w * h0v.w;
    float a1 = v1.x * h1v.x + v1.y * h1v.y + v1.z * h1v.z + v1.w * h1v.w;
    float a2 = v2.x * h2v.x + v2.y * h2v.y + v2.z * h2v.z + v2.w * h2v.w;
    float a3 = v3.x * h3v.x + v3.y * h3v.y + v3.z * h3v.z + v3.w * h3v.w;
    float acc = (a0 + a1) + (a2 + a3);
#pragma unroll
    for (int off = 16; off > 0; off >>= 1)
        acc += __shfl_xor_sync(0xFFFFFFFF, acc, off);

    if (lane == 0) {
        int mm = g_mask_mode;
        bool masked;
        size_t mi = (size_t)b * SS + s;
        if (mm == 0)      masked = ((const int*)maskp)[mi] != 0;
        else if (mm == 1) masked = ((const float*)maskp)[mi] != 0.f;
        else              masked = ((const unsigned char*)maskp)[mi] != 0;
        g_scores[mi] = masked ? -INFINITY : acc;
    }
}

// ---------------- softmax over S per batch row ----------------
__global__ void softmax_kernel() {
    int b = blockIdx.x;
    int tid = threadIdx.x;               // 256
    const float* sc = g_scores + (size_t)b * SS;
    __shared__ float red[256];
    float m = -INFINITY;
    for (int s = tid; s < SS; s += 256) m = fmaxf(m, sc[s]);
    red[tid] = m; __syncthreads();
    for (int o = 128; o > 0; o >>= 1) { if (tid < o) red[tid] = fmaxf(red[tid], red[tid + o]); __syncthreads(); }
    float mx = red[0]; __syncthreads();
    float sum = 0.f;
    for (int s = tid; s < SS; s += 256) sum += expf(sc[s] - mx);
    red[tid] = sum; __syncthreads();
    for (int o = 128; o > 0; o >>= 1) { if (tid < o) red[tid] += red[tid + o]; __syncthreads(); }
    float inv = 1.0f / red[0];
    float* w = g_attw + (size_t)b * SS;
    for (int s = tid; s < SS; s += 256) w[s] = expf(sc[s] - mx) * inv;
}

// ---------------- ctx partials: block per (chunk, b) ----------------
__global__ void ctx_part_kernel(const float* __restrict__ src) {
    int ch = blockIdx.x, b = blockIdx.y;
    int tid = threadIdx.x;               // 128, each owns float4 of E
    const int ROWS = SS / NCHUNK;        // 64
    __shared__ float w[ROWS];
    if (tid < ROWS) w[tid] = g_attw[(size_t)b * SS + ch * ROWS + tid];
    __syncthreads();
    const float4* base = (const float4*)(src + ((size_t)b * SS + (size_t)ch * ROWS) * EE);
    float4 acc = make_float4(0.f, 0.f, 0.f, 0.f);
#pragma unroll 8
    for (int s = 0; s < ROWS; s++) {
        float4 v = base[(size_t)s * 128 + tid];
        float ws = w[s];
        acc.x = fmaf(ws, v.x, acc.x);
        acc.y = fmaf(ws, v.y, acc.y);
        acc.z = fmaf(ws, v.z, acc.z);
        acc.w = fmaf(ws, v.w, acc.w);
    }
    ((float4*)g_part)[((size_t)b * NCHUNK + ch) * 128 + tid] = acc;
}

// ---------------- reduce ctx partials into g_hc[:, E:], float4 ----------------
__global__ void ctx_reduce4_kernel() {
    int idx = blockIdx.x * blockDim.x + threadIdx.x;   // 32*128
    int b = idx >> 7, e4 = idx & 127;
    float4 s = make_float4(0.f, 0.f, 0.f, 0.f);
#pragma unroll
    for (int c = 0; c < NCHUNK; c++) {
        float4 p = ((const float4*)g_part)[((size_t)b * NCHUNK + c) * 128 + e4];
        s.x += p.x; s.y += p.y; s.z += p.z; s.w += p.w;
    }
    ((float4*)(g_hc + (size_t)b * 2 * EE + EE))[e4] = s;
}

// ---------------- launch ----------------
extern "C" void kernel_launch(void* const* d_in, const int* in_sizes, int n_in,
                              void* d_out, int out_size) {
    const float* encoded_src     = (const float*)d_in[0];
    const float* encoded_src_att = (const float*)d_in[1];
    const float* encoded_col     = (const float*)d_in[2];
    const float* encoded_tab     = (const float*)d_in[3];
    const void*  src_mask        = d_in[4];
    const float* att             = (const float*)d_in[5];
    const float* h0              = (const float*)d_in[6];
    const float* c0              = (const float*)d_in[7];
    const int*   head_agg        = (const int*)d_in[8];
    const int*   head_col        = (const int*)d_in[9];
    const int*   quant_tab       = (const int*)d_in[10];
    const int*   box_op          = (const int*)d_in[11];
    const float* agg_emb         = (const float*)d_in[12];
    const float* box_op_emb      = (const float*)d_in[13];
    const float* W_box           = (const float*)d_in[14];
    const float* b_box           = (const float*)d_in[15];
    const float* W_ih            = (const float*)d_in[16];
    const float* W_hh            = (const float*)d_in[17];
    const float* b_ih            = (const float*)d_in[18];
    const float* b_hh            = (const float*)d_in[19];
    const float* W_att           = (const float*)d_in[20];
    const float* b_att           = (const float*)d_in[21];
    float* out = (float*)d_out;

    float *p_boxA, *p_lstmA, *p_pbox, *p_pgates, *p_patt, *p_hc;
    cudaGetSymbolAddress((void**)&p_boxA, g_boxA);
    cudaGetSymbolAddress((void**)&p_lstmA, g_lstmA);
    cudaGetSymbolAddress((void**)&p_hc, g_hc);
    cudaGetSymbolAddress((void**)&p_pbox, g_pbox);
    cudaGetSymbolAddress((void**)&p_pgates, g_pgates);
    cudaGetSymbolAddress((void**)&p_patt, g_patt);

    // 1. prep + mask sniff
    prep_detect_kernel<<<BB + 1, EE>>>(agg_emb, encoded_col, encoded_tab,
                                       box_op_emb, head_agg, head_col,
                                       quant_tab, box_op, att, h0,
                                       (const unsigned int*)src_mask);

    // 2. box GEMM partials (KC=32) + reduce+relu -> g_lstmA[:, :E]
    gemm_cp_kernel<<<dim3(EE / 64, CH_BOX), 128>>>(
        p_boxA, 3 * EE, W_box, 3 * EE, nullptr, p_pbox, EE);
    reduce_act4_kernel<<<(BB * EE / 4) / 256, 256>>>(
        (const float4*)p_pbox, CH_BOX, EE / 4, (const float4*)b_box,
        (float4*)p_lstmA, (3 * EE) / 4, 1);

    // 3. gates GEMM partials (KC=64)
    gemm_cp_kernel<<<dim3((4 * EE) / 64, CH_GATES), 128>>>(
        p_lstmA, 3 * EE, W_ih, 2 * EE, W_hh, p_pgates, 4 * EE);

    // 4. LSTM elementwise (reduces partials + biases) -> h in g_hc[:, :E]
    lstm_elem4_kernel<<<(BB * EE / 4) / 256, 256>>>(
        (const float4*)c0, (const float4*)b_ih, (const float4*)b_hh);

    // 5. attention scores (134 MB stream)
    scores_kernel<<<dim3(SS / 8, BB), 256>>>(encoded_src_att, src_mask);

    // 6. softmax
    softmax_kernel<<<BB, 256>>>();

    // 7. ctx partials (134 MB stream)
    ctx_part_kernel<<<dim3(NCHUNK, BB), 128>>>(encoded_src);

    // 8. reduce -> g_hc[:, E:]
    ctx_reduce4_kernel<<<(BB * EE / 4) / 256, 256>>>();

    // 9. att GEMM partials (KC=32) + reduce+relu -> d_out
    gemm_cp_kernel<<<dim3(EE / 64, CH_ATT), 128>>>(
        p_hc, 2 * EE, W_att, 2 * EE, nullptr, p_patt, EE);
    reduce_act4_kernel<<<(BB * EE / 4) / 256, 256>>>(
        (const float4*)p_patt, CH_ATT, EE / 4, (const float4*)b_att,
        (float4*)out, EE / 4, 1);
}

// round 13
// speedup vs baseline: 1.0584x; 1.0409x over previous
#include <cuda_runtime.h>
#include <cuda_bf16.h>
#include <math.h>

// Problem constants
#define BB   32
#define SS   2048
#define EE   512
#define NCc  128
#define NTt  32
#define HH   8
#define QQ   4

// split-K chunk counts (KC = K/chunks must be a multiple of 32)
#define CH_BOX   48
#define CH_GATES 24
#define CH_ATT   32

#define NCHUNK 32   // ctx partial chunks
#define NPAD   36   // shared row pad (floats): 16B-aligned rows

typedef unsigned long long ull;

// ---------------- device scratch (no allocations allowed) ----------------
__device__ float g_boxA [BB * 3 * EE];          // [head_emb | body_emb | box_op_e]
__device__ float g_lstmA[BB * 3 * EE];          // [encoded_box | att | h0]
__device__ float g_hc   [BB * 2 * EE];          // [h | ctx]
__device__ float g_scores[BB * SS];
__device__ float g_part  [BB * NCHUNK * EE];        // ctx partials
__device__ float g_pbox  [CH_BOX   * BB * EE];      // box gemm partials
__device__ float g_pgates[CH_GATES * BB * 4 * EE];  // gates gemm partials
__device__ float g_patt  [CH_ATT   * BB * EE];      // att gemm partials
__device__ int   g_mask_mode;                       // 0=int32, 1=float32, 2=uint8

__device__ __forceinline__ void ffma2(ull& d, ull a, ull b) {
    asm("fma.rn.f32x2 %0, %1, %2, %0;" : "+l"(d) : "l"(a), "l"(b));
}
__device__ __forceinline__ void cpa16(unsigned s, const void* g) {
    asm volatile("cp.async.cg.shared.global [%0], [%1], 16;" :: "r"(s), "l"(g));
}
__device__ __forceinline__ void cp_commit() {
    asm volatile("cp.async.commit_group;");
}
template <int N> __device__ __forceinline__ void cp_wait() {
    asm volatile("cp.async.wait_group %0;" :: "n"(N));
}

// ---------------- prep (blocks 0..31) + mask sniff (block 32) ----------------
__global__ void prep_detect_kernel(const float* __restrict__ agg_emb,
                                   const float* __restrict__ encoded_col,
                                   const float* __restrict__ encoded_tab,
                                   const float* __restrict__ box_op_emb,
                                   const int* __restrict__ head_agg,
                                   const int* __restrict__ head_col,
                                   const int* __restrict__ quant_tab,
                                   const int* __restrict__ box_op,
                                   const float* __restrict__ att,
                                   const float* __restrict__ h0,
                                   const unsigned int* __restrict__ maskw) {
    int e = threadIdx.x;                 // 512 threads
    if (blockIdx.x == BB) {
        __shared__ int s_ok32, s_okf;
        if (e == 0) { s_ok32 = 1; s_okf = 1; }
        __syncthreads();
        int ok32 = 1, okf = 1;
        for (int i = e; i < 2048; i += 512) {
            unsigned v = maskw[i];
            if (v > 1u) ok32 = 0;
            if (v != 0u && v != 0x3F800000u) okf = 0;
        }
        if (!ok32) atomicAnd(&s_ok32, 0);
        if (!okf)  atomicAnd(&s_okf, 0);
        __syncthreads();
        if (e == 0) g_mask_mode = s_ok32 ? 0 : (s_okf ? 1 : 2);
        return;
    }
    int b = blockIdx.x;
    __shared__ int ia[HH], ic[HH], iq[QQ], ib;
    if (e < HH) ia[e] = head_agg[b * HH + e];
    else if (e < 2 * HH) ic[e - HH] = head_col[b * HH + (e - HH)];
    else if (e < 2 * HH + QQ) iq[e - 2 * HH] = quant_tab[b * QQ + (e - 2 * HH)];
    else if (e == 2 * HH + QQ) ib = box_op[b];
    __syncthreads();

    float he = 0.f;
#pragma unroll
    for (int h = 0; h < HH; h++)
        he += agg_emb[ia[h] * EE + e] + encoded_col[((size_t)b * NCc + ic[h]) * EE + e];
    he *= (1.0f / HH);
    float be = 0.f;
#pragma unroll
    for (int q = 0; q < QQ; q++)
        be += encoded_tab[((size_t)b * NTt + iq[q]) * EE + e];
    be *= (1.0f / QQ);

    float* boxA = g_boxA + (size_t)b * 3 * EE;
    boxA[e]          = he;
    boxA[EE + e]     = be;
    boxA[2 * EE + e] = box_op_emb[ib * EE + e];

    float* lA = g_lstmA + (size_t)b * 3 * EE;
    lA[EE + e]     = att[b * EE + e];
    lA[2 * EE + e] = h0[b * EE + e];
}

// ---------------- cp.async + FFMA2 split-K GEMM (LDS.128 inner loop) --------
__global__ void __launch_bounds__(128)
gemm_cp_kernel(const float* __restrict__ A, int K,
               const float* __restrict__ W1, int K1,
               const float* __restrict__ W2,
               float* __restrict__ part, int Ntot) {
    __shared__ __align__(16) float As[2][32][NPAD];
    __shared__ __align__(16) float Ws[2][64][NPAD];
    int tid = threadIdx.x;               // 128
    int n0  = blockIdx.x * 64;
    int KC  = K / gridDim.y;
    int kb  = blockIdx.y * KC;
    int T   = KC / 32;
    int K2len = K - K1;

    unsigned as_s = (unsigned)__cvta_generic_to_shared(&As[0][0][0]);
    unsigned ws_s = (unsigned)__cvta_generic_to_shared(&Ws[0][0][0]);

    int q = tid & 7, r = tid >> 3;
    int ng = tid & 15, bg = tid >> 4;

    ull acc[4][4];
#pragma unroll
    for (int i = 0; i < 4; i++)
#pragma unroll
        for (int j = 0; j < 4; j++) acc[i][j] = 0ull;

#define G_LOAD(buf, k0)                                                        \
    {                                                                          \
        int kg = (k0) + q * 4;                                                 \
        _Pragma("unroll")                                                      \
        for (int m = 0; m < 4; m++) {                                          \
            int row = r + 16 * m;                                              \
            const float* src = (kg < K1)                                       \
                ? (W1 + (size_t)(n0 + row) * K1 + kg)                          \
                : (W2 + (size_t)(n0 + row) * K2len + (kg - K1));               \
            cpa16(ws_s + (unsigned)((((buf) * 64 + row) * NPAD + q * 4) * 4),  \
                  src);                                                        \
        }                                                                      \
        cpa16(as_s + (unsigned)((((buf) * 32 + r) * NPAD + q * 4) * 4),        \
              A + (size_t)r * K + kg);                                         \
        cpa16(as_s + (unsigned)((((buf) * 32 + r + 16) * NPAD + q * 4) * 4),   \
              A + (size_t)(r + 16) * K + kg);                                  \
        cp_commit();                                                           \
    }

    G_LOAD(0, kb);
    if (T > 1) G_LOAD(1, kb + 32);

    for (int t = 0; t < T; t++) {
        if (t + 1 < T) cp_wait<1>(); else cp_wait<0>();
        __syncthreads();
        int buf = t & 1;
#pragma unroll
        for (int k4 = 0; k4 < 8; k4++) {
            ulonglong2 a2[4], w2[4];
#pragma unroll
            for (int i = 0; i < 4; i++)
                a2[i] = *(const ulonglong2*)&As[buf][bg + 8 * i][k4 * 4];
#pragma unroll
            for (int j = 0; j < 4; j++)
                w2[j] = *(const ulonglong2*)&Ws[buf][ng + 16 * j][k4 * 4];
#pragma unroll
            for (int i = 0; i < 4; i++)
#pragma unroll
                for (int j = 0; j < 4; j++) {
                    ffma2(acc[i][j], a2[i].x, w2[j].x);
                    ffma2(acc[i][j], a2[i].y, w2[j].y);
                }
        }
        __syncthreads();
        if (t + 2 < T) G_LOAD(buf, kb + (t + 2) * 32);
    }

    float* dst = part + (size_t)(blockIdx.y * 32) * Ntot;
#pragma unroll
    for (int i = 0; i < 4; i++) {
        int b = bg + 8 * i;
#pragma unroll
        for (int j = 0; j < 4; j++) {
            int n = n0 + ng + 16 * j;
            ull v = acc[i][j];
            float lo = __uint_as_float((unsigned)(v & 0xFFFFFFFFull));
            float hi = __uint_as_float((unsigned)(v >> 32));
            dst[(size_t)b * Ntot + n] = lo + hi;
        }
    }
#undef G_LOAD
}

// ---------------- reduce split-K partials + bias (+relu), float4 ----------------
__global__ void reduce_act4_kernel(const float4* __restrict__ part, int nchunks,
                                   int N4, const float4* __restrict__ bias,
                                   float4* __restrict__ out, int ldo4, int relu) {
    int idx = blockIdx.x * blockDim.x + threadIdx.x;   // 32*N4 items
    int b = idx / N4, n = idx - b * N4;
    float4 s = make_float4(0.f, 0.f, 0.f, 0.f);
#pragma unroll 16
    for (int c = 0; c < nchunks; c++) {
        float4 p = part[(size_t)(c * 32 + b) * N4 + n];
        s.x += p.x; s.y += p.y; s.z += p.z; s.w += p.w;
    }
    float4 bb = bias[n];
    s.x += bb.x; s.y += bb.y; s.z += bb.z; s.w += bb.w;
    if (relu) {
        s.x = fmaxf(s.x, 0.f); s.y = fmaxf(s.y, 0.f);
        s.z = fmaxf(s.z, 0.f); s.w = fmaxf(s.w, 0.f);
    }
    out[(size_t)b * ldo4 + n] = s;
}

// ---------------- LSTM elementwise, float4, reduces gates partials ----------
__device__ __forceinline__ float sigmf(float x) { return 1.0f / (1.0f + expf(-x)); }

__global__ void lstm_elem4_kernel(const float4* __restrict__ c0,
                                  const float4* __restrict__ b_ih,
                                  const float4* __restrict__ b_hh) {
    int idx = blockIdx.x * blockDim.x + threadIdx.x;   // 32*128
    int b = idx >> 7, e4 = idx & 127;
    float4 gi = make_float4(0,0,0,0), gf = gi, gg = gi, go = gi;
#pragma unroll
    for (int c = 0; c < CH_GATES; c++) {
        const float4* g = (const float4*)(g_pgates + (size_t)(c * 32 + b) * 4 * EE);
        float4 a = g[e4], f = g[128 + e4], x = g[256 + e4], o = g[384 + e4];
        gi.x += a.x; gi.y += a.y; gi.z += a.z; gi.w += a.w;
        gf.x += f.x; gf.y += f.y; gf.z += f.z; gf.w += f.w;
        gg.x += x.x; gg.y += x.y; gg.z += x.z; gg.w += x.w;
        go.x += o.x; go.y += o.y; go.z += o.z; go.w += o.w;
    }
    float4 bi = b_ih[e4],        bh = b_hh[e4];
    float4 bf = b_ih[128 + e4],  bf2 = b_hh[128 + e4];
    float4 bg = b_ih[256 + e4],  bg2 = b_hh[256 + e4];
    float4 bo = b_ih[384 + e4],  bo2 = b_hh[384 + e4];
    gi.x += bi.x + bh.x;  gi.y += bi.y + bh.y;  gi.z += bi.z + bh.z;  gi.w += bi.w + bh.w;
    gf.x += bf.x + bf2.x; gf.y += bf.y + bf2.y; gf.z += bf.z + bf2.z; gf.w += bf.w + bf2.w;
    gg.x += bg.x + bg2.x; gg.y += bg.y + bg2.y; gg.z += bg.z + bg2.z; gg.w += bg.w + bg2.w;
    go.x += bo.x + bo2.x; go.y += bo.y + bo2.y; go.z += bo.z + bo2.z; go.w += bo.w + bo2.w;
    float4 cc = c0[b * 128 + e4];
    float4 h;
    {
        float c1 = sigmf(gf.x) * cc.x + sigmf(gi.x) * tanhf(gg.x); h.x = sigmf(go.x) * tanhf(c1);
        float c2 = sigmf(gf.y) * cc.y + sigmf(gi.y) * tanhf(gg.y); h.y = sigmf(go.y) * tanhf(c2);
        float c3 = sigmf(gf.z) * cc.z + sigmf(gi.z) * tanhf(gg.z); h.z = sigmf(go.z) * tanhf(c3);
        float c4 = sigmf(gf.w) * cc.w + sigmf(gi.w) * tanhf(gg.w); h.w = sigmf(go.w) * tanhf(c4);
    }
    ((float4*)g_hc)[(size_t)b * 256 + e4] = h;   // h into [b][0:512)
}

// ---------------- attention scores: 4 rows per warp ----------------
__global__ void scores_kernel(const float* __restrict__ src_att,
                              const void* __restrict__ maskp) {
    int b = blockIdx.y;
    int tid = threadIdx.x;               // 256 = 8 warps, 32 rows per block
    __shared__ __align__(16) float sh[EE];
    for (int i = tid; i < EE; i += 256) sh[i] = g_hc[(size_t)b * 2 * EE + i];
    __syncthreads();

    int warp = tid >> 5, lane = tid & 31;
    const float4* h4 = (const float4*)sh;
    float4 h0v = h4[lane +  0];
    float4 h1v = h4[lane + 32];
    float4 h2v = h4[lane + 64];
    float4 h3v = h4[lane + 96];
    int mm = g_mask_mode;

#pragma unroll
    for (int rr = 0; rr < 4; rr++) {
        int s = blockIdx.x * 32 + warp * 4 + rr;
        const float4* row = (const float4*)(src_att + ((size_t)b * SS + s) * EE);
        float4 v0 = row[lane +  0];
        float4 v1 = row[lane + 32];
        float4 v2 = row[lane + 64];
        float4 v3 = row[lane + 96];
        float a0 = v0.x * h0v.x + v0.y * h0v.y + v0.z * h0v.z + v0.w * h0v.w;
        float a1 = v1.x * h1v.x + v1.y * h1v.y + v1.z * h1v.z + v1.w * h1v.w;
        float a2 = v2.x * h2v.x + v2.y * h2v.y + v2.z * h2v.z + v2.w * h2v.w;
        float a3 = v3.x * h3v.x + v3.y * h3v.y + v3.z * h3v.z + v3.w * h3v.w;
        float acc = (a0 + a1) + (a2 + a3);
#pragma unroll
        for (int off = 16; off > 0; off >>= 1)
            acc += __shfl_xor_sync(0xFFFFFFFF, acc, off);
        if (lane == 0) {
            bool masked;
            size_t mi = (size_t)b * SS + s;
            if (mm == 0)      masked = ((const int*)maskp)[mi] != 0;
            else if (mm == 1) masked = ((const float*)maskp)[mi] != 0.f;
            else              masked = ((const unsigned char*)maskp)[mi] != 0;
            g_scores[mi] = masked ? -INFINITY : acc;
        }
    }
}

// ---------------- ctx partials with fused softmax: block per (chunk, b) -----
__global__ void ctx_part_kernel(const float* __restrict__ src) {
    int ch = blockIdx.x, b = blockIdx.y;
    int tid = threadIdx.x;               // 128, each owns float4 of E
    const int ROWS = SS / NCHUNK;        // 64
    __shared__ float w[ROWS];
    __shared__ float red[128];

    // ---- local softmax derivation from the full score row (8 KB, L2-hot) ----
    const float* sc = g_scores + (size_t)b * SS;
    float m = -INFINITY;
#pragma unroll
    for (int i = 0; i < SS / 128; i++) m = fmaxf(m, sc[tid + i * 128]);
    red[tid] = m; __syncthreads();
    for (int o = 64; o > 0; o >>= 1) { if (tid < o) red[tid] = fmaxf(red[tid], red[tid + o]); __syncthreads(); }
    float M = red[0]; __syncthreads();
    float ssum = 0.f;
#pragma unroll
    for (int i = 0; i < SS / 128; i++) ssum += expf(sc[tid + i * 128] - M);
    red[tid] = ssum; __syncthreads();
    for (int o = 64; o > 0; o >>= 1) { if (tid < o) red[tid] += red[tid + o]; __syncthreads(); }
    float inv = 1.0f / red[0];
    __syncthreads();
    if (tid < ROWS) w[tid] = expf(sc[ch * ROWS + tid] - M) * inv;
    __syncthreads();

    // ---- weighted accumulation over this chunk's 64 rows ----
    const float4* base = (const float4*)(src + ((size_t)b * SS + (size_t)ch * ROWS) * EE);
    float4 acc = make_float4(0.f, 0.f, 0.f, 0.f);
#pragma unroll 8
    for (int s = 0; s < ROWS; s++) {
        float4 v = base[(size_t)s * 128 + tid];
        float ws = w[s];
        acc.x = fmaf(ws, v.x, acc.x);
        acc.y = fmaf(ws, v.y, acc.y);
        acc.z = fmaf(ws, v.z, acc.z);
        acc.w = fmaf(ws, v.w, acc.w);
    }
    ((float4*)g_part)[((size_t)b * NCHUNK + ch) * 128 + tid] = acc;
}

// ---------------- reduce ctx partials into g_hc[:, E:], float4 ----------------
__global__ void ctx_reduce4_kernel() {
    int idx = blockIdx.x * blockDim.x + threadIdx.x;   // 32*128
    int b = idx >> 7, e4 = idx & 127;
    float4 s = make_float4(0.f, 0.f, 0.f, 0.f);
#pragma unroll
    for (int c = 0; c < NCHUNK; c++) {
        float4 p = ((const float4*)g_part)[((size_t)b * NCHUNK + c) * 128 + e4];
        s.x += p.x; s.y += p.y; s.z += p.z; s.w += p.w;
    }
    ((float4*)(g_hc + (size_t)b * 2 * EE + EE))[e4] = s;
}

// ---------------- launch ----------------
extern "C" void kernel_launch(void* const* d_in, const int* in_sizes, int n_in,
                              void* d_out, int out_size) {
    const float* encoded_src     = (const float*)d_in[0];
    const float* encoded_src_att = (const float*)d_in[1];
    const float* encoded_col     = (const float*)d_in[2];
    const float* encoded_tab     = (const float*)d_in[3];
    const void*  src_mask        = d_in[4];
    const float* att             = (const float*)d_in[5];
    const float* h0              = (const float*)d_in[6];
    const float* c0              = (const float*)d_in[7];
    const int*   head_agg        = (const int*)d_in[8];
    const int*   head_col        = (const int*)d_in[9];
    const int*   quant_tab       = (const int*)d_in[10];
    const int*   box_op          = (const int*)d_in[11];
    const float* agg_emb         = (const float*)d_in[12];
    const float* box_op_emb      = (const float*)d_in[13];
    const float* W_box           = (const float*)d_in[14];
    const float* b_box           = (const float*)d_in[15];
    const float* W_ih            = (const float*)d_in[16];
    const float* W_hh            = (const float*)d_in[17];
    const float* b_ih            = (const float*)d_in[18];
    const float* b_hh            = (const float*)d_in[19];
    const float* W_att           = (const float*)d_in[20];
    const float* b_att           = (const float*)d_in[21];
    float* out = (float*)d_out;

    float *p_boxA, *p_lstmA, *p_pbox, *p_pgates, *p_patt, *p_hc;
    cudaGetSymbolAddress((void**)&p_boxA, g_boxA);
    cudaGetSymbolAddress((void**)&p_lstmA, g_lstmA);
    cudaGetSymbolAddress((void**)&p_hc, g_hc);
    cudaGetSymbolAddress((void**)&p_pbox, g_pbox);
    cudaGetSymbolAddress((void**)&p_pgates, g_pgates);
    cudaGetSymbolAddress((void**)&p_patt, g_patt);

    // 1. prep + mask sniff
    prep_detect_kernel<<<BB + 1, EE>>>(agg_emb, encoded_col, encoded_tab,
                                       box_op_emb, head_agg, head_col,
                                       quant_tab, box_op, att, h0,
                                       (const unsigned int*)src_mask);

    // 2. box GEMM partials + reduce+relu -> g_lstmA[:, :E]
    gemm_cp_kernel<<<dim3(EE / 64, CH_BOX), 128>>>(
        p_boxA, 3 * EE, W_box, 3 * EE, nullptr, p_pbox, EE);
    reduce_act4_kernel<<<(BB * EE / 4) / 256, 256>>>(
        (const float4*)p_pbox, CH_BOX, EE / 4, (const float4*)b_box,
        (float4*)p_lstmA, (3 * EE) / 4, 1);

    // 3. gates GEMM partials
    gemm_cp_kernel<<<dim3((4 * EE) / 64, CH_GATES), 128>>>(
        p_lstmA, 3 * EE, W_ih, 2 * EE, W_hh, p_pgates, 4 * EE);

    // 4. LSTM elementwise (reduces partials + biases) -> h in g_hc[:, :E]
    lstm_elem4_kernel<<<(BB * EE / 4) / 256, 256>>>(
        (const float4*)c0, (const float4*)b_ih, (const float4*)b_hh);

    // 5. attention scores (134 MB stream, 4 rows/warp)
    scores_kernel<<<dim3(SS / 32, BB), 256>>>(encoded_src_att, src_mask);

    // 6. ctx partials with fused softmax (134 MB stream)
    ctx_part_kernel<<<dim3(NCHUNK, BB), 128>>>(encoded_src);

    // 7. reduce -> g_hc[:, E:]
    ctx_reduce4_kernel<<<(BB * EE / 4) / 256, 256>>>();

    // 8. att GEMM partials + reduce+relu -> d_out
    gemm_cp_kernel<<<dim3(EE / 64, CH_ATT), 128>>>(
        p_hc, 2 * EE, W_att, 2 * EE, nullptr, p_patt, EE);
    reduce_act4_kernel<<<(BB * EE / 4) / 256, 256>>>(
        (const float4*)p_patt, CH_ATT, EE / 4, (const float4*)b_att,
        (float4*)out, EE / 4, 1);
}